// round 5
// baseline (speedup 1.0000x reference)
#include <cuda_runtime.h>
#include <cuda_fp16.h>

#define NN   50000
#define EE   1600000
#define DD   128
#define KK   16
#define ALPHA_F 0.05f
#define CW_F    (0.95f / 16.0f)
#define NPAD 50048
#define NBLK 49            // ceil(NN/1024)
#define ROW32 (NPAD * 32)  // uint2 groups per buffer

// -------------------- scratch (static device globals; no allocs) ------------
// 17 fp16 feature buffers: [0] = half(x0), [k] = A_hat^k x0, k=1..16
__device__ uint2 g_xbuf[(KK + 1) * ROW32];     // ~217 MB
__device__ int   g_deg[NN];
__device__ float g_dinv[NN];
__device__ int   g_rowptr[NN + 1];
__device__ int   g_cursor[NN];
__device__ int2  g_edge[EE];                   // (col, bitcast weight)
__device__ float g_Wt[DD * DD];
__device__ int   g_bsum[NBLK];
__device__ int   g_boff[NBLK];

// -------------------- prep kernels ------------------------------------------
__global__ void init_deg_kernel() {
    int v = blockIdx.x * blockDim.x + threadIdx.x;
    if (v < NN) { g_deg[v] = 1; g_cursor[v] = 0; }
}

__global__ void count_deg_kernel(const int* __restrict__ dst) {
    for (int e = blockIdx.x * blockDim.x + threadIdx.x; e < EE;
         e += gridDim.x * blockDim.x) {
        atomicAdd(&g_deg[dst[e]], 1);
    }
}

__global__ void dinv_kernel() {
    int v = blockIdx.x * blockDim.x + threadIdx.x;
    if (v < NN) g_dinv[v] = rsqrtf((float)g_deg[v]);
}

__device__ __forceinline__ int block_scan_inc(int v, int tid) {
    __shared__ int ws[32];
    const int lane = tid & 31, wid = tid >> 5;
    int x = v;
    #pragma unroll
    for (int d = 1; d < 32; d <<= 1) {
        int y = __shfl_up_sync(0xffffffffu, x, d);
        if (lane >= d) x += y;
    }
    if (lane == 31) ws[wid] = x;
    __syncthreads();
    if (wid == 0) {
        int s = ws[lane];
        int t = s;
        #pragma unroll
        for (int d = 1; d < 32; d <<= 1) {
            int y = __shfl_up_sync(0xffffffffu, t, d);
            if (lane >= d) t += y;
        }
        ws[lane] = t - s;
    }
    __syncthreads();
    return x + ws[wid];
}

__global__ void scan1_kernel() {
    __shared__ int ws[32];
    int tid = threadIdx.x;
    int i = blockIdx.x * 1024 + tid;
    int v = (i < NN) ? (g_deg[i] - 1) : 0;
    #pragma unroll
    for (int d = 16; d > 0; d >>= 1) v += __shfl_down_sync(0xffffffffu, v, d);
    if ((tid & 31) == 0) ws[tid >> 5] = v;
    __syncthreads();
    if (tid < 32) {
        int s = ws[tid];
        #pragma unroll
        for (int d = 16; d > 0; d >>= 1) s += __shfl_down_sync(0xffffffffu, s, d);
        if (tid == 0) g_bsum[blockIdx.x] = s;
    }
}

__global__ void scan2_kernel() {
    int tid = threadIdx.x;
    int v = (tid < NBLK) ? g_bsum[tid] : 0;
    int inc = block_scan_inc(v, tid);
    if (tid < NBLK) g_boff[tid] = inc - v;
    if (tid == 0) g_rowptr[NN] = EE;
}

__global__ void scan3_kernel() {
    int tid = threadIdx.x;
    int i = blockIdx.x * 1024 + tid;
    int v = (i < NN) ? (g_deg[i] - 1) : 0;
    int inc = block_scan_inc(v, tid);
    if (i < NN) g_rowptr[i] = inc - v + g_boff[blockIdx.x];
}

__global__ void scatter_kernel(const int* __restrict__ src,
                               const int* __restrict__ dst) {
    for (int e = blockIdx.x * blockDim.x + threadIdx.x; e < EE;
         e += gridDim.x * blockDim.x) {
        int s = src[e];
        int d = dst[e];
        int pos = g_rowptr[d] + atomicAdd(&g_cursor[d], 1);
        float w = g_dinv[s] * g_dinv[d];
        g_edge[pos] = make_int2(s, __float_as_int(w));
    }
}

__global__ void transpose_w_kernel(const float* __restrict__ W) {
    int o = threadIdx.x;
    int i = blockIdx.x;
    g_Wt[i * DD + o] = W[o * DD + i];
}

// x16[0] = half(x0)
__global__ void xinit_kernel(const float* __restrict__ x0) {
    int idx = blockIdx.x * blockDim.x + threadIdx.x;
    const int total = NN * 32;
    if (idx >= total) return;
    float4 v = ((const float4*)x0)[idx];
    __half2 p01 = __floats2half2_rn(v.x, v.y);
    __half2 p23 = __floats2half2_rn(v.z, v.w);
    uint2 o;
    o.x = *(unsigned int*)&p01;
    o.y = *(unsigned int*)&p23;
    g_xbuf[idx] = o;
}

// -------------------- hop: one warp per node, lane owns 4 fp16 features -----
__device__ __forceinline__ void acc_edge(float4& acc, uint2 r, float w) {
    float2 f01 = __half22float2(*(__half2*)&r.x);
    float2 f23 = __half22float2(*(__half2*)&r.y);
    acc.x += w * f01.x; acc.y += w * f01.y;
    acc.z += w * f23.x; acc.w += w * f23.y;
}

__global__ void __launch_bounds__(256)
hop_kernel(const uint2* __restrict__ xin, uint2* __restrict__ xout) {
    const int warp = (blockIdx.x * blockDim.x + threadIdx.x) >> 5;
    const int lane = threadIdx.x & 31;
    if (warp >= NN) return;

    const float dv = g_dinv[warp];
    uint2 xr = __ldg(&xin[warp * 32 + lane]);
    float4 acc = {0.f, 0.f, 0.f, 0.f};
    acc_edge(acc, xr, dv * dv);

    const int start = g_rowptr[warp];
    const int len   = g_deg[warp] - 1;

    for (int base = 0; base < len; base += 32) {
        int idx = start + base + lane;
        int   c = 0;
        float w = 0.0f;
        if (base + lane < len) {
            int2 e = __ldg(&g_edge[idx]);
            c = e.x;
            w = __int_as_float(e.y);
        }
        int rem = len - base; if (rem > 32) rem = 32;
        int j = 0;
        for (; j + 8 <= rem; j += 8) {
            int   s0 = __shfl_sync(0xffffffffu, c, j + 0);
            int   s1 = __shfl_sync(0xffffffffu, c, j + 1);
            int   s2 = __shfl_sync(0xffffffffu, c, j + 2);
            int   s3 = __shfl_sync(0xffffffffu, c, j + 3);
            int   s4 = __shfl_sync(0xffffffffu, c, j + 4);
            int   s5 = __shfl_sync(0xffffffffu, c, j + 5);
            int   s6 = __shfl_sync(0xffffffffu, c, j + 6);
            int   s7 = __shfl_sync(0xffffffffu, c, j + 7);
            float w0 = __shfl_sync(0xffffffffu, w, j + 0);
            float w1 = __shfl_sync(0xffffffffu, w, j + 1);
            float w2 = __shfl_sync(0xffffffffu, w, j + 2);
            float w3 = __shfl_sync(0xffffffffu, w, j + 3);
            float w4 = __shfl_sync(0xffffffffu, w, j + 4);
            float w5 = __shfl_sync(0xffffffffu, w, j + 5);
            float w6 = __shfl_sync(0xffffffffu, w, j + 6);
            float w7 = __shfl_sync(0xffffffffu, w, j + 7);
            uint2 v0 = __ldg(&xin[s0 * 32 + lane]);
            uint2 v1 = __ldg(&xin[s1 * 32 + lane]);
            uint2 v2 = __ldg(&xin[s2 * 32 + lane]);
            uint2 v3 = __ldg(&xin[s3 * 32 + lane]);
            uint2 v4 = __ldg(&xin[s4 * 32 + lane]);
            uint2 v5 = __ldg(&xin[s5 * 32 + lane]);
            uint2 v6 = __ldg(&xin[s6 * 32 + lane]);
            uint2 v7 = __ldg(&xin[s7 * 32 + lane]);
            acc_edge(acc, v0, w0);
            acc_edge(acc, v1, w1);
            acc_edge(acc, v2, w2);
            acc_edge(acc, v3, w3);
            acc_edge(acc, v4, w4);
            acc_edge(acc, v5, w5);
            acc_edge(acc, v6, w6);
            acc_edge(acc, v7, w7);
        }
        for (; j < rem; j++) {
            int   s0 = __shfl_sync(0xffffffffu, c, j);
            float w0 = __shfl_sync(0xffffffffu, w, j);
            uint2 v0 = __ldg(&xin[s0 * 32 + lane]);
            acc_edge(acc, v0, w0);
        }
    }

    __half2 o01 = __floats2half2_rn(acc.x, acc.y);
    __half2 o23 = __floats2half2_rn(acc.z, acc.w);
    uint2 ow;
    ow.x = *(unsigned int*)&o01;
    ow.y = *(unsigned int*)&o23;
    xout[warp * 32 + lane] = ow;
}

// -------------------- fused sum + GEMM: out = (a*x0 + c*Sum xk) @ W^T + b ---
#define GEMM_NODES 32
__global__ void __launch_bounds__(128)
fused_kernel(const float* __restrict__ x0, const float* __restrict__ bias,
             float* __restrict__ out) {
    __shared__ float4 sh[GEMM_NODES * 32];      // 16 KB (32 nodes x 128 feats)

    const int o = threadIdx.x;
    float w[DD];
    #pragma unroll
    for (int i = 0; i < DD; i++) w[i] = g_Wt[i * DD + o];
    const float b = bias[o];

    const int node0 = blockIdx.x * GEMM_NODES;

    // stage h tile: thread t handles slots t, t+128, ... (8 slots)
    #pragma unroll
    for (int s = threadIdx.x; s < GEMM_NODES * 32; s += 128) {
        int n = s >> 5;          // node within tile
        int g = s & 31;          // uint2 group (4 features)
        int node = node0 + n;
        float4 acc = {0.f, 0.f, 0.f, 0.f};
        if (node < NN) {
            float4 v0 = __ldg(&((const float4*)x0)[node * 32 + g]);
            acc.x = ALPHA_F * v0.x; acc.y = ALPHA_F * v0.y;
            acc.z = ALPHA_F * v0.z; acc.w = ALPHA_F * v0.w;
            const uint2* p = &g_xbuf[ROW32 + node * 32 + g];  // buffer k=1
            #pragma unroll
            for (int k = 0; k < KK; k++) {
                uint2 r = __ldg(p + k * ROW32);
                acc_edge(acc, r, CW_F);
            }
        }
        sh[s] = acc;
    }
    __syncthreads();

    for (int nn = 0; nn < GEMM_NODES; nn++) {
        int node = node0 + nn;
        if (node >= NN) break;
        float acc = b;
        #pragma unroll
        for (int i = 0; i < DD; i += 4) {
            float4 hh = sh[nn * 32 + (i >> 2)];
            acc += hh.x * w[i] + hh.y * w[i + 1] + hh.z * w[i + 2] + hh.w * w[i + 3];
        }
        out[node * DD + o] = acc;
    }
}

// -------------------- launch -------------------------------------------------
extern "C" void kernel_launch(void* const* d_in, const int* in_sizes, int n_in,
                              void* d_out, int out_size) {
    const float* x0   = (const float*)d_in[0];
    const int*   ei   = (const int*)  d_in[1];
    const float* W    = (const float*)d_in[2];
    const float* bias = (const float*)d_in[3];
    const int* src = ei;
    const int* dst = ei + EE;
    float* out = (float*)d_out;

    void* pX;
    cudaGetSymbolAddress(&pX, g_xbuf);
    uint2* xb = (uint2*)pX;

    init_deg_kernel<<<(NN + 255) / 256, 256>>>();
    count_deg_kernel<<<2048, 256>>>(dst);
    dinv_kernel<<<(NN + 255) / 256, 256>>>();
    scan1_kernel<<<NBLK, 1024>>>();
    scan2_kernel<<<1, 1024>>>();
    scan3_kernel<<<NBLK, 1024>>>();
    scatter_kernel<<<2048, 256>>>(src, dst);
    transpose_w_kernel<<<DD, DD>>>(W);
    xinit_kernel<<<(NN * 32 + 255) / 256, 256>>>(x0);

    for (int k = 0; k < KK; k++) {
        hop_kernel<<<(NN + 7) / 8, 256>>>(xb + k * ROW32, xb + (k + 1) * ROW32);
    }

    fused_kernel<<<(NN + GEMM_NODES - 1) / GEMM_NODES, 128>>>(x0, bias, out);
}